// round 2
// baseline (speedup 1.0000x reference)
#include <cuda_runtime.h>

// Row-normalize: out[b,i,j] = adj[b,i,j] / sum_j adj[b,i,j]  (nan/inf inv -> 0)
// Shapes: two tensors of [16, 1024, 1024] fp32. Output = concat(out0, out1).
//
// One CTA per row. 256 threads x float4 = 1024 elements held in registers:
// single read pass, block reduction for the degree, scale, single write pass.

constexpr int N = 1024;           // row length
constexpr int THREADS = 256;      // N / 4 elements per thread as float4

__global__ __launch_bounds__(THREADS, 8)
void row_norm_kernel(const float* __restrict__ in0,
                     const float* __restrict__ in1,
                     float* __restrict__ out,
                     int rows_per_tensor)   // B*N = 16384
{
    const int row = blockIdx.x;             // 0 .. 2*rows_per_tensor-1
    const bool second = row >= rows_per_tensor;
    const float* __restrict__ src = second ? in1 : in0;
    const long long local_row = second ? (row - rows_per_tensor) : row;

    const float4* __restrict__ src_row =
        reinterpret_cast<const float4*>(src + local_row * (long long)N);
    float4* __restrict__ dst_row =
        reinterpret_cast<float4*>(out + (long long)row * N);

    const int t = threadIdx.x;

    // Single global read: one float4 per thread, kept in registers.
    float4 v = src_row[t];

    float partial = (v.x + v.y) + (v.z + v.w);

    // Warp reduction
    #pragma unroll
    for (int off = 16; off > 0; off >>= 1)
        partial += __shfl_xor_sync(0xFFFFFFFFu, partial, off);

    // Block reduction across 8 warps
    __shared__ float warp_sums[THREADS / 32];
    __shared__ float inv_s;
    const int lane = t & 31;
    const int wid  = t >> 5;
    if (lane == 0) warp_sums[wid] = partial;
    __syncthreads();

    if (t == 0) {
        float deg = 0.f;
        #pragma unroll
        for (int w = 0; w < THREADS / 32; ++w) deg += warp_sums[w];
        float inv = 1.0f / deg;
        // match reference: nan/inf -> 0
        if (!isfinite(inv)) inv = 0.0f;
        inv_s = inv;
    }
    __syncthreads();

    const float inv = inv_s;
    v.x *= inv; v.y *= inv; v.z *= inv; v.w *= inv;
    dst_row[t] = v;
}

extern "C" void kernel_launch(void* const* d_in, const int* in_sizes, int n_in,
                              void* d_out, int out_size)
{
    const float* adj0 = (const float*)d_in[0];
    const float* adj1 = (const float*)d_in[1];
    float* out = (float*)d_out;

    const int rows_per_tensor = in_sizes[0] / N;   // 16*1024 = 16384
    const int total_rows = 2 * rows_per_tensor;    // 32768

    row_norm_kernel<<<total_rows, THREADS>>>(adj0, adj1, out, rows_per_tensor);
}

// round 5
// speedup vs baseline: 1.0768x; 1.0768x over previous
#include <cuda_runtime.h>

// Row-normalize: out[b,i,j] = adj[b,i,j] / sum_j adj[b,i,j]  (nan/inf inv -> 0)
// Two tensors of [16, 1024, 1024] fp32; output = concat(out0, out1).
//
// 2 rows per CTA, 128 threads/row, 2 float4 per thread (MLP=2).
// Single __syncthreads per CTA; every thread re-sums the 4 warp partials
// itself (no broadcast barrier). Streaming cache hints (no reuse).

constexpr int N            = 1024;                 // row length
constexpr int THREADS      = 256;
constexpr int ROWS_PER_CTA = 2;
constexpr int TPR          = THREADS / ROWS_PER_CTA;  // 128 threads per row
constexpr int WARPS_PER_ROW = TPR / 32;               // 4

__global__ __launch_bounds__(THREADS, 8)
void row_norm_kernel(const float* __restrict__ in0,
                     const float* __restrict__ in1,
                     float* __restrict__ out,
                     int rows_per_tensor)   // 16384
{
    const int tid    = threadIdx.x;
    const int rgroup = tid >> 7;            // 0 or 1: which row in this CTA
    const int t      = tid & (TPR - 1);     // lane within the row group

    const long long row = (long long)blockIdx.x * ROWS_PER_CTA + rgroup;
    const bool second = row >= rows_per_tensor;
    const float* __restrict__ src = second ? in1 : in0;
    const long long local_row = second ? (row - rows_per_tensor) : row;

    const float4* __restrict__ src_row =
        reinterpret_cast<const float4*>(src) + local_row * (N / 4);
    float4* __restrict__ dst_row =
        reinterpret_cast<float4*>(out) + row * (N / 4);

    // Two independent 128B loads in flight per thread.
    float4 v0 = __ldcs(src_row + t);
    float4 v1 = __ldcs(src_row + t + TPR);

    float partial = ((v0.x + v0.y) + (v0.z + v0.w))
                  + ((v1.x + v1.y) + (v1.z + v1.w));

    // Warp reduction (each warp is entirely within one row group)
    #pragma unroll
    for (int off = 16; off > 0; off >>= 1)
        partial += __shfl_xor_sync(0xFFFFFFFFu, partial, off);

    __shared__ float warp_sums[THREADS / 32];   // 8: warps 0-3 row0, 4-7 row1
    const int wid = tid >> 5;
    if ((tid & 31) == 0) warp_sums[wid] = partial;
    __syncthreads();

    // Every thread sums its row's 4 warp partials — no broadcast barrier.
    const float* ws = &warp_sums[rgroup * WARPS_PER_ROW];
    float deg = (ws[0] + ws[1]) + (ws[2] + ws[3]);
    float inv = 1.0f / deg;
    if (!isfinite(inv)) inv = 0.0f;

    v0.x *= inv; v0.y *= inv; v0.z *= inv; v0.w *= inv;
    v1.x *= inv; v1.y *= inv; v1.z *= inv; v1.w *= inv;
    __stcs(dst_row + t,        v0);
    __stcs(dst_row + t + TPR,  v1);
}

extern "C" void kernel_launch(void* const* d_in, const int* in_sizes, int n_in,
                              void* d_out, int out_size)
{
    const float* adj0 = (const float*)d_in[0];
    const float* adj1 = (const float*)d_in[1];
    float* out = (float*)d_out;

    const int rows_per_tensor = in_sizes[0] / N;          // 16384
    const int total_rows = 2 * rows_per_tensor;           // 32768
    const int grid = total_rows / ROWS_PER_CTA;           // 16384

    row_norm_kernel<<<grid, THREADS>>>(adj0, adj1, out, rows_per_tensor);
}